// round 1
// baseline (speedup 1.0000x reference)
#include <cuda_runtime.h>
#include <cstdint>

#define S_LEN    2048
#define DHEAD    128
#define NHEADS   64          // B*H = 4*16
#define BR       128         // query rows per CTA
#define BC       128         // keys per tile
#define NTHREADS 256
#define PS_STRIDE 132        // P smem row stride (floats), mult of 4 for float4

// 2048*2048 bits = 512 KB packed mask scratch (allocation-free)
__device__ uint32_t g_mask_bits[(size_t)S_LEN * S_LEN / 32];

// ---------------------------------------------------------------------------
// Pre-kernel: pack int32 mask [S,S] -> bitmask. word w covers row w/64,
// cols (w%64)*32 .. +31 ; since w*32 == row*2048 + col0, flat int4 loads work.
// ---------------------------------------------------------------------------
__global__ void pack_mask_kernel(const int* __restrict__ mask) {
    int w = blockIdx.x * blockDim.x + threadIdx.x;
    if (w >= S_LEN * S_LEN / 32) return;
    const int4* m4 = reinterpret_cast<const int4*>(mask) + (size_t)w * 8;
    uint32_t b = 0;
#pragma unroll
    for (int i = 0; i < 8; i++) {
        int4 v = m4[i];
        b |= (uint32_t)(v.x != 0) << (i * 4 + 0);
        b |= (uint32_t)(v.y != 0) << (i * 4 + 1);
        b |= (uint32_t)(v.z != 0) << (i * 4 + 2);
        b |= (uint32_t)(v.w != 0) << (i * 4 + 3);
    }
    g_mask_bits[w] = b;
}

// ---------------------------------------------------------------------------
// Register-transposed tile load: src [128 rows][128] row-major (global)
//   -> dst [128 d][128 rows] (smem). 4x4 register transpose; smem stores are
// contiguous float4 (conflict-free).
// ---------------------------------------------------------------------------
__device__ __forceinline__ void load_tile_T(float* dst, const float* __restrict__ src, int tid) {
#pragma unroll
    for (int it = 0; it < 4; it++) {
        int b  = it * NTHREADS + tid;     // 0..1023
        int r0 = (b & 31) << 2;           // row block
        int d0 = (b >> 5) << 2;           // d block
        float4 g0 = *reinterpret_cast<const float4*>(src + (r0 + 0) * DHEAD + d0);
        float4 g1 = *reinterpret_cast<const float4*>(src + (r0 + 1) * DHEAD + d0);
        float4 g2 = *reinterpret_cast<const float4*>(src + (r0 + 2) * DHEAD + d0);
        float4 g3 = *reinterpret_cast<const float4*>(src + (r0 + 3) * DHEAD + d0);
        *reinterpret_cast<float4*>(dst + (d0 + 0) * BR + r0) = make_float4(g0.x, g1.x, g2.x, g3.x);
        *reinterpret_cast<float4*>(dst + (d0 + 1) * BR + r0) = make_float4(g0.y, g1.y, g2.y, g3.y);
        *reinterpret_cast<float4*>(dst + (d0 + 2) * BR + r0) = make_float4(g0.z, g1.z, g2.z, g3.z);
        *reinterpret_cast<float4*>(dst + (d0 + 3) * BR + r0) = make_float4(g0.w, g1.w, g2.w, g3.w);
    }
}

// ---------------------------------------------------------------------------
// Flash attention, fp32 SIMT. Grid: (S/BR, NHEADS). Block: 256 threads (16x16).
// Thread (ty,tx): S tile rows ty*8..+7, cols tx*8..+7 ; O cols tx*8..+7 of 128.
// ---------------------------------------------------------------------------
__global__ void __launch_bounds__(NTHREADS, 1)
flash_fp32_kernel(const float* __restrict__ Q, const float* __restrict__ K,
                  const float* __restrict__ V, float* __restrict__ Out)
{
    extern __shared__ float sm[];
    float* qt = sm;                        // [128 d][128 r]   16384 f
    float* kv = sm + BR * DHEAD;           // K: [d][c] / V: [c][d]  16384 f
    float* ps = sm + 2 * BR * DHEAD;       // P: [128 r][PS_STRIDE]  16896 f

    const int tid = threadIdx.x;
    const int ty  = tid >> 4;
    const int tx  = tid & 15;
    const int bh  = blockIdx.y;
    const int q0  = blockIdx.x * BR;

    const size_t base = (size_t)bh * S_LEN * DHEAD;
    const float* qg = Q + base + (size_t)q0 * DHEAD;
    const float* kg = K + base;
    const float* vg = V + base;

    const float scale_l2e = 1.4426950408889634f / sqrtf(128.0f); // log2(e)/sqrt(D)

    load_tile_T(qt, qg, tid);

    float m[8], l[8], O[8][8];
#pragma unroll
    for (int i = 0; i < 8; i++) {
        m[i] = -1e30f; l[i] = 0.f;
#pragma unroll
        for (int j = 0; j < 8; j++) O[i][j] = 0.f;
    }
    __syncthreads();   // qt visible

    for (int kt = 0; kt < S_LEN / BC; kt++) {
        const int k0 = kt * BC;

        // ---- stage K (transposed) ----
        load_tile_T(kv, kg + (size_t)k0 * DHEAD, tid);
        __syncthreads();

        // ---- S = Q K^T (8x8 per thread) ----
        float s[8][8];
#pragma unroll
        for (int i = 0; i < 8; i++)
#pragma unroll
            for (int j = 0; j < 8; j++) s[i][j] = 0.f;

#pragma unroll 4
        for (int d = 0; d < DHEAD; d++) {
            float4 qa = *reinterpret_cast<const float4*>(qt + d * BR + ty * 8);
            float4 qb = *reinterpret_cast<const float4*>(qt + d * BR + ty * 8 + 4);
            float4 ka = *reinterpret_cast<const float4*>(kv + d * BC + tx * 8);
            float4 kb = *reinterpret_cast<const float4*>(kv + d * BC + tx * 8 + 4);
            float qv[8] = {qa.x, qa.y, qa.z, qa.w, qb.x, qb.y, qb.z, qb.w};
            float kvv[8] = {ka.x, ka.y, ka.z, ka.w, kb.x, kb.y, kb.z, kb.w};
#pragma unroll
            for (int i = 0; i < 8; i++)
#pragma unroll
                for (int j = 0; j < 8; j++) s[i][j] = fmaf(qv[i], kvv[j], s[i][j]);
        }
        __syncthreads();   // done reading K tile

        // ---- stage V (natural [c][d]) — overlapped with softmax math ----
        {
            const float4* vsrc = reinterpret_cast<const float4*>(vg + (size_t)k0 * DHEAD);
            float4* vdst = reinterpret_cast<float4*>(kv);
#pragma unroll
            for (int i = 0; i < (BC * DHEAD / 4) / NTHREADS; i++)
                vdst[i * NTHREADS + tid] = vsrc[i * NTHREADS + tid];
        }

        // ---- mask + scale (log2 domain) ----
#pragma unroll
        for (int i = 0; i < 8; i++) {
            uint32_t w = g_mask_bits[(size_t)(q0 + ty * 8 + i) * (S_LEN / 32) + (k0 >> 5) + (tx >> 2)];
            uint32_t bits = w >> ((tx & 3) * 8);
#pragma unroll
            for (int j = 0; j < 8; j++)
                s[i][j] = ((bits >> j) & 1u) ? s[i][j] * scale_l2e : -1e30f;
        }

        // ---- online softmax (rows reduced across 16 tx lanes) ----
#pragma unroll
        for (int i = 0; i < 8; i++) {
            float mt = s[i][0];
#pragma unroll
            for (int j = 1; j < 8; j++) mt = fmaxf(mt, s[i][j]);
            mt = fmaxf(mt, __shfl_xor_sync(0xffffffffu, mt, 1));
            mt = fmaxf(mt, __shfl_xor_sync(0xffffffffu, mt, 2));
            mt = fmaxf(mt, __shfl_xor_sync(0xffffffffu, mt, 4));
            mt = fmaxf(mt, __shfl_xor_sync(0xffffffffu, mt, 8));
            float mnew  = fmaxf(m[i], mt);
            float alpha = exp2f(m[i] - mnew);
            m[i] = mnew;
            float rs = 0.f;
#pragma unroll
            for (int j = 0; j < 8; j++) {
                s[i][j] = exp2f(s[i][j] - mnew);
                rs += s[i][j];
            }
            rs += __shfl_xor_sync(0xffffffffu, rs, 1);
            rs += __shfl_xor_sync(0xffffffffu, rs, 2);
            rs += __shfl_xor_sync(0xffffffffu, rs, 4);
            rs += __shfl_xor_sync(0xffffffffu, rs, 8);
            l[i] = l[i] * alpha + rs;
#pragma unroll
            for (int j = 0; j < 8; j++) O[i][j] *= alpha;
        }

        // ---- write P to smem ----
#pragma unroll
        for (int i = 0; i < 8; i++) {
            *reinterpret_cast<float4*>(ps + (ty * 8 + i) * PS_STRIDE + tx * 8) =
                make_float4(s[i][0], s[i][1], s[i][2], s[i][3]);
            *reinterpret_cast<float4*>(ps + (ty * 8 + i) * PS_STRIDE + tx * 8 + 4) =
                make_float4(s[i][4], s[i][5], s[i][6], s[i][7]);
        }
        __syncthreads();   // V + P visible

        // ---- O += P V (8 rows x 8 dcols per thread) ----
#pragma unroll 2
        for (int c4 = 0; c4 < BC / 4; c4++) {
            float4 pf[8];
#pragma unroll
            for (int i = 0; i < 8; i++)
                pf[i] = *reinterpret_cast<const float4*>(ps + (ty * 8 + i) * PS_STRIDE + c4 * 4);
#pragma unroll
            for (int cc = 0; cc < 4; cc++) {
                float4 va = *reinterpret_cast<const float4*>(kv + (c4 * 4 + cc) * DHEAD + tx * 8);
                float4 vb = *reinterpret_cast<const float4*>(kv + (c4 * 4 + cc) * DHEAD + tx * 8 + 4);
#pragma unroll
                for (int i = 0; i < 8; i++) {
                    const float* pfi = reinterpret_cast<const float*>(&pf[i]);
                    float p = pfi[cc];
                    O[i][0] = fmaf(p, va.x, O[i][0]);
                    O[i][1] = fmaf(p, va.y, O[i][1]);
                    O[i][2] = fmaf(p, va.z, O[i][2]);
                    O[i][3] = fmaf(p, va.w, O[i][3]);
                    O[i][4] = fmaf(p, vb.x, O[i][4]);
                    O[i][5] = fmaf(p, vb.y, O[i][5]);
                    O[i][6] = fmaf(p, vb.z, O[i][6]);
                    O[i][7] = fmaf(p, vb.w, O[i][7]);
                }
            }
        }
        __syncthreads();   // done reading V & P before next K stage
    }

    // ---- epilogue: normalize and store ----
    float* og = Out + base + (size_t)q0 * DHEAD;
#pragma unroll
    for (int i = 0; i < 8; i++) {
        float inv = 1.0f / l[i];
        *reinterpret_cast<float4*>(og + (ty * 8 + i) * DHEAD + tx * 8) =
            make_float4(O[i][0] * inv, O[i][1] * inv, O[i][2] * inv, O[i][3] * inv);
        *reinterpret_cast<float4*>(og + (ty * 8 + i) * DHEAD + tx * 8 + 4) =
            make_float4(O[i][4] * inv, O[i][5] * inv, O[i][6] * inv, O[i][7] * inv);
    }
}

// ---------------------------------------------------------------------------
extern "C" void kernel_launch(void* const* d_in, const int* in_sizes, int n_in,
                              void* d_out, int out_size)
{
    const float* q    = reinterpret_cast<const float*>(d_in[0]);
    const float* k    = reinterpret_cast<const float*>(d_in[1]);
    const float* v    = reinterpret_cast<const float*>(d_in[2]);
    const int*   mask = reinterpret_cast<const int*>(d_in[3]);
    float* out = reinterpret_cast<float*>(d_out);

    // pack mask -> bits (serializes before main kernel on same stream)
    const int nwords = S_LEN * S_LEN / 32;
    pack_mask_kernel<<<(nwords + 255) / 256, 256>>>(mask);

    const int smem_bytes = (BR * DHEAD + BC * DHEAD + BR * PS_STRIDE) * (int)sizeof(float);
    static bool attr_set = false;
    if (!attr_set) {
        cudaFuncSetAttribute(flash_fp32_kernel,
                             cudaFuncAttributeMaxDynamicSharedMemorySize, smem_bytes);
        attr_set = true;
    }

    dim3 grid(S_LEN / BR, NHEADS);
    flash_fp32_kernel<<<grid, NTHREADS, smem_bytes>>>(q, k, v, out);
}

// round 2
// speedup vs baseline: 1.0013x; 1.0013x over previous
#include <cuda_runtime.h>
#include <cstdint>

#define S_LEN    2048
#define DHEAD    128
#define NHEADS   64          // B*H = 4*16
#define BR       128         // query rows per CTA
#define BC       128         // keys per tile
#define NTHREADS 256
#define PS_STRIDE 132        // P smem row stride (floats), mult of 4 for float4

// 2048*2048 bits = 512 KB packed mask scratch (allocation-free)
__device__ uint32_t g_mask_bits[(size_t)S_LEN * S_LEN / 32];

// ---------------------------------------------------------------------------
// Pre-kernel: pack int32 mask [S,S] -> bitmask. word w covers row w/64,
// cols (w%64)*32 .. +31 ; since w*32 == row*2048 + col0, flat int4 loads work.
// ---------------------------------------------------------------------------
__global__ void pack_mask_kernel(const int* __restrict__ mask) {
    int w = blockIdx.x * blockDim.x + threadIdx.x;
    if (w >= S_LEN * S_LEN / 32) return;
    const int4* m4 = reinterpret_cast<const int4*>(mask) + (size_t)w * 8;
    uint32_t b = 0;
#pragma unroll
    for (int i = 0; i < 8; i++) {
        int4 v = m4[i];
        b |= (uint32_t)(v.x != 0) << (i * 4 + 0);
        b |= (uint32_t)(v.y != 0) << (i * 4 + 1);
        b |= (uint32_t)(v.z != 0) << (i * 4 + 2);
        b |= (uint32_t)(v.w != 0) << (i * 4 + 3);
    }
    g_mask_bits[w] = b;
}

// ---------------------------------------------------------------------------
// Register-transposed tile load: src [128 rows][128] row-major (global)
//   -> dst [128 d][128 rows] (smem). 4x4 register transpose; smem stores are
// contiguous float4 (conflict-free).
// ---------------------------------------------------------------------------
__device__ __forceinline__ void load_tile_T(float* dst, const float* __restrict__ src, int tid) {
#pragma unroll
    for (int it = 0; it < 4; it++) {
        int b  = it * NTHREADS + tid;     // 0..1023
        int r0 = (b & 31) << 2;           // row block
        int d0 = (b >> 5) << 2;           // d block
        float4 g0 = *reinterpret_cast<const float4*>(src + (r0 + 0) * DHEAD + d0);
        float4 g1 = *reinterpret_cast<const float4*>(src + (r0 + 1) * DHEAD + d0);
        float4 g2 = *reinterpret_cast<const float4*>(src + (r0 + 2) * DHEAD + d0);
        float4 g3 = *reinterpret_cast<const float4*>(src + (r0 + 3) * DHEAD + d0);
        *reinterpret_cast<float4*>(dst + (d0 + 0) * BR + r0) = make_float4(g0.x, g1.x, g2.x, g3.x);
        *reinterpret_cast<float4*>(dst + (d0 + 1) * BR + r0) = make_float4(g0.y, g1.y, g2.y, g3.y);
        *reinterpret_cast<float4*>(dst + (d0 + 2) * BR + r0) = make_float4(g0.z, g1.z, g2.z, g3.z);
        *reinterpret_cast<float4*>(dst + (d0 + 3) * BR + r0) = make_float4(g0.w, g1.w, g2.w, g3.w);
    }
}

// ---------------------------------------------------------------------------
// Flash attention, fp32 SIMT. Grid: (S/BR, NHEADS). Block: 256 threads (16x16).
// Thread (ty,tx): S tile rows ty*8..+7, cols tx*8..+7 ; O cols tx*8..+7 of 128.
// ---------------------------------------------------------------------------
__global__ void __launch_bounds__(NTHREADS, 1)
flash_fp32_kernel(const float* __restrict__ Q, const float* __restrict__ K,
                  const float* __restrict__ V, float* __restrict__ Out)
{
    extern __shared__ float sm[];
    float* qt = sm;                        // [128 d][128 r]   16384 f
    float* kv = sm + BR * DHEAD;           // K: [d][c] / V: [c][d]  16384 f
    float* ps = sm + 2 * BR * DHEAD;       // P: [128 r][PS_STRIDE]  16896 f

    const int tid = threadIdx.x;
    const int ty  = tid >> 4;
    const int tx  = tid & 15;
    const int bh  = blockIdx.y;
    const int q0  = blockIdx.x * BR;

    const size_t base = (size_t)bh * S_LEN * DHEAD;
    const float* qg = Q + base + (size_t)q0 * DHEAD;
    const float* kg = K + base;
    const float* vg = V + base;

    const float scale_l2e = 1.4426950408889634f / sqrtf(128.0f); // log2(e)/sqrt(D)

    load_tile_T(qt, qg, tid);

    float m[8], l[8], O[8][8];
#pragma unroll
    for (int i = 0; i < 8; i++) {
        m[i] = -1e30f; l[i] = 0.f;
#pragma unroll
        for (int j = 0; j < 8; j++) O[i][j] = 0.f;
    }
    __syncthreads();   // qt visible

    for (int kt = 0; kt < S_LEN / BC; kt++) {
        const int k0 = kt * BC;

        // ---- stage K (transposed) ----
        load_tile_T(kv, kg + (size_t)k0 * DHEAD, tid);
        __syncthreads();

        // ---- S = Q K^T (8x8 per thread) ----
        float s[8][8];
#pragma unroll
        for (int i = 0; i < 8; i++)
#pragma unroll
            for (int j = 0; j < 8; j++) s[i][j] = 0.f;

#pragma unroll 4
        for (int d = 0; d < DHEAD; d++) {
            float4 qa = *reinterpret_cast<const float4*>(qt + d * BR + ty * 8);
            float4 qb = *reinterpret_cast<const float4*>(qt + d * BR + ty * 8 + 4);
            float4 ka = *reinterpret_cast<const float4*>(kv + d * BC + tx * 8);
            float4 kb = *reinterpret_cast<const float4*>(kv + d * BC + tx * 8 + 4);
            float qv[8] = {qa.x, qa.y, qa.z, qa.w, qb.x, qb.y, qb.z, qb.w};
            float kvv[8] = {ka.x, ka.y, ka.z, ka.w, kb.x, kb.y, kb.z, kb.w};
#pragma unroll
            for (int i = 0; i < 8; i++)
#pragma unroll
                for (int j = 0; j < 8; j++) s[i][j] = fmaf(qv[i], kvv[j], s[i][j]);
        }
        __syncthreads();   // done reading K tile

        // ---- stage V (natural [c][d]) — overlapped with softmax math ----
        {
            const float4* vsrc = reinterpret_cast<const float4*>(vg + (size_t)k0 * DHEAD);
            float4* vdst = reinterpret_cast<float4*>(kv);
#pragma unroll
            for (int i = 0; i < (BC * DHEAD / 4) / NTHREADS; i++)
                vdst[i * NTHREADS + tid] = vsrc[i * NTHREADS + tid];
        }

        // ---- mask + scale (log2 domain) ----
#pragma unroll
        for (int i = 0; i < 8; i++) {
            uint32_t w = g_mask_bits[(size_t)(q0 + ty * 8 + i) * (S_LEN / 32) + (k0 >> 5) + (tx >> 2)];
            uint32_t bits = w >> ((tx & 3) * 8);
#pragma unroll
            for (int j = 0; j < 8; j++)
                s[i][j] = ((bits >> j) & 1u) ? s[i][j] * scale_l2e : -1e30f;
        }

        // ---- online softmax (rows reduced across 16 tx lanes) ----
#pragma unroll
        for (int i = 0; i < 8; i++) {
            float mt = s[i][0];
#pragma unroll
            for (int j = 1; j < 8; j++) mt = fmaxf(mt, s[i][j]);
            mt = fmaxf(mt, __shfl_xor_sync(0xffffffffu, mt, 1));
            mt = fmaxf(mt, __shfl_xor_sync(0xffffffffu, mt, 2));
            mt = fmaxf(mt, __shfl_xor_sync(0xffffffffu, mt, 4));
            mt = fmaxf(mt, __shfl_xor_sync(0xffffffffu, mt, 8));
            float mnew  = fmaxf(m[i], mt);
            float alpha = exp2f(m[i] - mnew);
            m[i] = mnew;
            float rs = 0.f;
#pragma unroll
            for (int j = 0; j < 8; j++) {
                s[i][j] = exp2f(s[i][j] - mnew);
                rs += s[i][j];
            }
            rs += __shfl_xor_sync(0xffffffffu, rs, 1);
            rs += __shfl_xor_sync(0xffffffffu, rs, 2);
            rs += __shfl_xor_sync(0xffffffffu, rs, 4);
            rs += __shfl_xor_sync(0xffffffffu, rs, 8);
            l[i] = l[i] * alpha + rs;
#pragma unroll
            for (int j = 0; j < 8; j++) O[i][j] *= alpha;
        }

        // ---- write P to smem ----
#pragma unroll
        for (int i = 0; i < 8; i++) {
            *reinterpret_cast<float4*>(ps + (ty * 8 + i) * PS_STRIDE + tx * 8) =
                make_float4(s[i][0], s[i][1], s[i][2], s[i][3]);
            *reinterpret_cast<float4*>(ps + (ty * 8 + i) * PS_STRIDE + tx * 8 + 4) =
                make_float4(s[i][4], s[i][5], s[i][6], s[i][7]);
        }
        __syncthreads();   // V + P visible

        // ---- O += P V (8 rows x 8 dcols per thread) ----
#pragma unroll 2
        for (int c4 = 0; c4 < BC / 4; c4++) {
            float4 pf[8];
#pragma unroll
            for (int i = 0; i < 8; i++)
                pf[i] = *reinterpret_cast<const float4*>(ps + (ty * 8 + i) * PS_STRIDE + c4 * 4);
#pragma unroll
            for (int cc = 0; cc < 4; cc++) {
                float4 va = *reinterpret_cast<const float4*>(kv + (c4 * 4 + cc) * DHEAD + tx * 8);
                float4 vb = *reinterpret_cast<const float4*>(kv + (c4 * 4 + cc) * DHEAD + tx * 8 + 4);
#pragma unroll
                for (int i = 0; i < 8; i++) {
                    const float* pfi = reinterpret_cast<const float*>(&pf[i]);
                    float p = pfi[cc];
                    O[i][0] = fmaf(p, va.x, O[i][0]);
                    O[i][1] = fmaf(p, va.y, O[i][1]);
                    O[i][2] = fmaf(p, va.z, O[i][2]);
                    O[i][3] = fmaf(p, va.w, O[i][3]);
                    O[i][4] = fmaf(p, vb.x, O[i][4]);
                    O[i][5] = fmaf(p, vb.y, O[i][5]);
                    O[i][6] = fmaf(p, vb.z, O[i][6]);
                    O[i][7] = fmaf(p, vb.w, O[i][7]);
                }
            }
        }
        __syncthreads();   // done reading V & P before next K stage
    }

    // ---- epilogue: normalize and store ----
    float* og = Out + base + (size_t)q0 * DHEAD;
#pragma unroll
    for (int i = 0; i < 8; i++) {
        float inv = 1.0f / l[i];
        *reinterpret_cast<float4*>(og + (ty * 8 + i) * DHEAD + tx * 8) =
            make_float4(O[i][0] * inv, O[i][1] * inv, O[i][2] * inv, O[i][3] * inv);
        *reinterpret_cast<float4*>(og + (ty * 8 + i) * DHEAD + tx * 8 + 4) =
            make_float4(O[i][4] * inv, O[i][5] * inv, O[i][6] * inv, O[i][7] * inv);
    }
}

// ---------------------------------------------------------------------------
extern "C" void kernel_launch(void* const* d_in, const int* in_sizes, int n_in,
                              void* d_out, int out_size)
{
    const float* q    = reinterpret_cast<const float*>(d_in[0]);
    const float* k    = reinterpret_cast<const float*>(d_in[1]);
    const float* v    = reinterpret_cast<const float*>(d_in[2]);
    const int*   mask = reinterpret_cast<const int*>(d_in[3]);
    float* out = reinterpret_cast<float*>(d_out);

    // pack mask -> bits (serializes before main kernel on same stream)
    const int nwords = S_LEN * S_LEN / 32;
    pack_mask_kernel<<<(nwords + 255) / 256, 256>>>(mask);

    const int smem_bytes = (BR * DHEAD + BC * DHEAD + BR * PS_STRIDE) * (int)sizeof(float);
    static bool attr_set = false;
    if (!attr_set) {
        cudaFuncSetAttribute(flash_fp32_kernel,
                             cudaFuncAttributeMaxDynamicSharedMemorySize, smem_bytes);
        attr_set = true;
    }

    dim3 grid(S_LEN / BR, NHEADS);
    flash_fp32_kernel<<<grid, NTHREADS, smem_bytes>>>(q, k, v, out);
}